// round 9
// baseline (speedup 1.0000x reference)
#include <cuda_runtime.h>
#include <cstdint>

// Problem constants
#define B_DIM   4
#define Z_DIM   128
#define IN_DIM  512
#define R_DIM   256
#define M_DIM   2048          // B*Z*D*V flattened rows of the projections

// Scratch for the three projections p1,p2,p3 : [3][2048][256] fp32 = 6 MB
__device__ float g_p[3][M_DIM * R_DIM];

// ---------------- packed f32x2 helpers (sm_100+ PTX) ----------------
static __device__ __forceinline__ unsigned long long pack2(float lo, float hi) {
    unsigned long long r;
    asm("mov.b64 %0, {%1, %2};" : "=l"(r) : "f"(lo), "f"(hi));
    return r;
}
static __device__ __forceinline__ void unpack2(unsigned long long v, float& lo, float& hi) {
    asm("mov.b64 {%0, %1}, %2;" : "=f"(lo), "=f"(hi) : "l"(v));
}
static __device__ __forceinline__ unsigned long long fma2(unsigned long long a,
                                                          unsigned long long b,
                                                          unsigned long long c) {
    unsigned long long d;
    asm("fma.rn.f32x2 %0, %1, %2, %3;" : "=l"(d) : "l"(a), "l"(b), "l"(c));
    return d;
}
static __device__ __forceinline__ unsigned long long mul2(unsigned long long a,
                                                          unsigned long long b) {
    unsigned long long d;
    asm("mul.rn.f32x2 %0, %1, %2;" : "=l"(d) : "l"(a), "l"(b));
    return d;
}
static __device__ __forceinline__ unsigned long long add2(unsigned long long a,
                                                          unsigned long long b) {
    unsigned long long d;
    asm("add.rn.f32x2 %0, %1, %2;" : "=l"(d) : "l"(a), "l"(b));
    return d;
}

// =====================================================================
// Fused projections: p[w][m][r] = sum_i xw[m][i] * Ww[i][r] + bw[r]
// which = blockIdx.z.  M=2048, K=512, N=256.
// Block tile 128m x 128r, 256 threads, micro-tile 8m x 8r.
// =====================================================================
__global__ __launch_bounds__(256, 2)
void proj_kernel(const float* __restrict__ x1, const float* __restrict__ x2,
                 const float* __restrict__ x3,
                 const float* __restrict__ W1, const float* __restrict__ b1,
                 const float* __restrict__ W2, const float* __restrict__ b2,
                 const float* __restrict__ W3, const float* __restrict__ b3) {
    __shared__ float              Xs[128 * 17];          // [m][kk], pitch 17
    __shared__ unsigned long long Ws2[16 * 65];          // [kk][r-pair], pitch 65

    const int which = blockIdx.z;
    const float* x    = (which == 0) ? x1 : (which == 1) ? x2 : x3;
    const float* W    = (which == 0) ? W1 : (which == 1) ? W2 : W3;
    const float* bias = (which == 0) ? b1 : (which == 1) ? b2 : b3;
    float* __restrict__ p = g_p[which];

    const int tid = threadIdx.x;
    const int rT  = tid & 15;          // 16 r-thread groups
    const int mT  = tid >> 4;          // 16 m-thread groups
    const int r0  = blockIdx.x * 128;
    const int m0  = blockIdx.y * 128;

    unsigned long long acc[8][4];
#pragma unroll
    for (int i = 0; i < 8; ++i)
#pragma unroll
        for (int j = 0; j < 4; ++j) acc[i][j] = 0ull;

    for (int k0 = 0; k0 < IN_DIM; k0 += 16) {
        __syncthreads();
        // X tile [128m][16k] (global coalesced along k)
#pragma unroll
        for (int i = tid; i < 128 * 16; i += 256) {
            int m = i >> 4, kk = i & 15;
            Xs[m * 17 + kk] = x[(size_t)(m0 + m) * IN_DIM + k0 + kk];
        }
        // W tile as r-pairs [16k][64 pairs]
#pragma unroll
        for (int i = tid; i < 16 * 64; i += 256) {
            int kk = i >> 6, pp = i & 63;
            float2 w = *(const float2*)&W[(size_t)(k0 + kk) * R_DIM + r0 + 2 * pp];
            Ws2[kk * 65 + pp] = pack2(w.x, w.y);
        }
        __syncthreads();

#pragma unroll 2
        for (int kk = 0; kk < 16; ++kk) {
            unsigned long long w2[4];
#pragma unroll
            for (int j = 0; j < 4; ++j) w2[j] = Ws2[kk * 65 + rT + 16 * j];
#pragma unroll
            for (int i = 0; i < 8; ++i) {
                float a = Xs[(mT * 8 + i) * 17 + kk];
                unsigned long long a2 = pack2(a, a);
#pragma unroll
                for (int j = 0; j < 4; ++j) acc[i][j] = fma2(a2, w2[j], acc[i][j]);
            }
        }
    }

    // bias + store (8B stores, r-contiguous, aligned; default caching so the
    // trilinear kernel finds g_p in L2)
#pragma unroll
    for (int j = 0; j < 4; ++j) {
        float2 bb = *(const float2*)&bias[r0 + 2 * (rT + 16 * j)];
        unsigned long long b2 = pack2(bb.x, bb.y);
#pragma unroll
        for (int i = 0; i < 8; ++i) {
            unsigned long long v = add2(acc[i][j], b2);
            *(unsigned long long*)&p[(size_t)(m0 + mT * 8 + i) * R_DIM + r0 + 2 * (rT + 16 * j)] = v;
        }
    }
}

// =====================================================================
// Trilinear: out[b,z,x,c,d,v] = sum_e p1[z-row][e] p2[x-row][e] p3[c-row][e]
// f32x2 lanes packed over v (the output's innermost dim) -> aligned STG.64.
// Per block: one (b,d) slice, tile 32z x 8x x 64c x 2v, 256 threads.
// Per thread: 4z x 2x x 8c v-pair accumulators (64 f32x2 = 128 outputs).
// e-loop: 8 tiles of 32 = FULL R_DIM=256.
// Register-prefetch pipeline hides LDG latency under the FMA loop.
// All compute-phase shared loads are LDS.64, broadcast or conflict-free.
// Output uses DEFAULT store policy: the d=0/d=1 half-sector writes of each
// 128B line merge in L2 (output ~fits in 126MB L2) -> ~1x DRAM writeback.
// g_p row for (b,pos,d,v) = (b*128+pos)*4 + d*2 + v, each row 256 floats.
// =====================================================================
#define NTILE (R_DIM / 32)   // 8 e-tiles

__global__ __launch_bounds__(256, 1)
void trilinear_kernel(float* __restrict__ out) {
    __shared__ unsigned long long As2[32 * 33];         // [z][e] {v0,v1}, pitch 33
    __shared__ unsigned long long Bs2[32 * 9];          // [e][x]  {v0,v1}, pitch 9
    __shared__ unsigned long long Cs [32 * 65];         // [e][c]  {v0,v1}, pitch 65

    const int tid = threadIdx.x;
    const int tcT = tid & 7;            // 8 c-groups (c = tcT + 8*i)
    const int txT = (tid >> 3) & 3;     // 4 x-groups  (x = txT + 4*j)
    const int tzT = tid >> 5;           // 8 z-groups  (z = tzT*4 + k); warp-uniform

    const int c0 = blockIdx.x * 64;     // 2 c-tiles
    const int x0 = blockIdx.y * 8;      // 16 x-tiles
    const int s  = blockIdx.z >> 2;     // slice 0..7  = (b,d)
    const int z0 = (blockIdx.z & 3) * 32;
    const int b  = s >> 1;
    const int d  = s & 1;

    const float* __restrict__ P1 = g_p[0];
    const float* __restrict__ P2 = g_p[1];
    const float* __restrict__ P3 = g_p[2];

    unsigned long long acc[4][2][8];
#pragma unroll
    for (int k = 0; k < 4; ++k)
#pragma unroll
        for (int j = 0; j < 2; ++j)
#pragma unroll
            for (int i = 0; i < 8; ++i) acc[k][j][i] = 0ull;

    // row(pos, v) = (b*128 + pos)*4 + d*2 + v   (units: g_p rows of 256 floats)
    const int rbase = b * 128 * 4 + d * 2;      // + pos*4 + v

    // Per-thread fixed load lanes (e = tid&31 contiguous -> coalesced LDG):
    //   A: entries i = tid + 256q, q<4 : z = i>>5, e = tid&31     (32z x 32e)
    //   B: one entry: x = tid>>5, e = tid&31                      ( 8x x 32e)
    //   C: entries i = tid + 256q, q<8 : c = i>>5, e = tid&31     (64c x 32e)
    const int eL = tid & 31;
    const int zq[4] = { tid >> 5, (tid + 256) >> 5, (tid + 512) >> 5, (tid + 768) >> 5 };
    const int xL = tid >> 5;

    float pa0[4], pa1[4], pb0, pb1, pc0[8], pc1[8];

    // ---- prologue: load first e-tile (e0 = 0) ----
#pragma unroll
    for (int q = 0; q < 4; ++q) {
        size_t r = (size_t)(rbase + (z0 + zq[q]) * 4) * R_DIM + eL;
        pa0[q] = P1[r];
        pa1[q] = P1[r + R_DIM];     // v=1 row is +1 row = +256 floats
    }
    {
        size_t r = (size_t)(rbase + (x0 + xL) * 4) * R_DIM + eL;
        pb0 = P2[r];
        pb1 = P2[r + R_DIM];
    }
#pragma unroll
    for (int q = 0; q < 8; ++q) {
        int c = (tid + 256 * q) >> 5;
        size_t r = (size_t)(rbase + (c0 + c) * 4) * R_DIM + eL;
        pc0[q] = P3[r];
        pc1[q] = P3[r + R_DIM];
    }

    for (int t = 0; t < NTILE; ++t) {
        __syncthreads();
#pragma unroll
        for (int q = 0; q < 4; ++q)
            As2[zq[q] * 33 + eL] = pack2(pa0[q], pa1[q]);
        Bs2[eL * 9 + xL] = pack2(pb0, pb1);
#pragma unroll
        for (int q = 0; q < 8; ++q) {
            int c = (tid + 256 * q) >> 5;
            Cs[eL * 65 + c] = pack2(pc0[q], pc1[q]);
        }
        __syncthreads();

        // Issue next tile's global loads NOW; latency hides under compute.
        if (t < NTILE - 1) {
            const int e0n = (t + 1) * 32;
#pragma unroll
            for (int q = 0; q < 4; ++q) {
                size_t r = (size_t)(rbase + (z0 + zq[q]) * 4) * R_DIM + e0n + eL;
                pa0[q] = P1[r];
                pa1[q] = P1[r + R_DIM];
            }
            {
                size_t r = (size_t)(rbase + (x0 + xL) * 4) * R_DIM + e0n + eL;
                pb0 = P2[r];
                pb1 = P2[r + R_DIM];
            }
#pragma unroll
            for (int q = 0; q < 8; ++q) {
                int c = (tid + 256 * q) >> 5;
                size_t r = (size_t)(rbase + (c0 + c) * 4) * R_DIM + e0n + eL;
                pc0[q] = P3[r];
                pc1[q] = P3[r + R_DIM];
            }
        }

#pragma unroll 2
        for (int e = 0; e < 32; ++e) {
            unsigned long long c2[8];
#pragma unroll
            for (int i = 0; i < 8; ++i) c2[i] = Cs[e * 65 + tcT + 8 * i];
            unsigned long long b2v[2];
            b2v[0] = Bs2[e * 9 + txT];
            b2v[1] = Bs2[e * 9 + txT + 4];
#pragma unroll
            for (int k = 0; k < 4; ++k) {
                unsigned long long a2 = As2[(tzT * 4 + k) * 33 + e];  // warp-uniform
#pragma unroll
                for (int j = 0; j < 2; ++j) {
                    unsigned long long pz = mul2(a2, b2v[j]);
#pragma unroll
                    for (int i = 0; i < 8; ++i)
                        acc[k][j][i] = fma2(pz, c2[i], acc[k][j][i]);
                }
            }
        }
    }

    // Store: out flat = (((b*128+z)*128 + x)*128 + c)*4 + d*2 + v.
    // Each acc holds {v0,v1} -> one aligned 8-byte store (default policy).
#pragma unroll
    for (int k = 0; k < 4; ++k) {
        int z = z0 + tzT * 4 + k;
#pragma unroll
        for (int j = 0; j < 2; ++j) {
            int x = x0 + txT + 4 * j;
            size_t base = ((size_t)((b * 128 + z) * 128 + x) * 128 + c0) * 4 + d * 2;
#pragma unroll
            for (int i = 0; i < 8; ++i) {
                float lo, hi;
                unpack2(acc[k][j][i], lo, hi);
                *(float2*)&out[base + (size_t)(tcT + 8 * i) * 4] = make_float2(lo, hi);
            }
        }
    }
}

// =====================================================================
extern "C" void kernel_launch(void* const* d_in, const int* in_sizes, int n_in,
                              void* d_out, int out_size) {
    const float* x1 = (const float*)d_in[0];
    const float* x2 = (const float*)d_in[1];
    const float* x3 = (const float*)d_in[2];
    const float* W1 = (const float*)d_in[3];
    const float* b1 = (const float*)d_in[4];
    const float* W2 = (const float*)d_in[5];
    const float* b2 = (const float*)d_in[6];
    const float* W3 = (const float*)d_in[7];
    const float* b3 = (const float*)d_in[8];
    float* out = (float*)d_out;

    // All three projections in one launch: grid (2 r-tiles, 16 m-tiles, 3 proj)
    proj_kernel<<<dim3(2, 16, 3), 256>>>(x1, x2, x3, W1, b1, W2, b2, W3, b3);

    // grid: (c-tiles=2, x-tiles=16, slices*z-tiles = 8*4 = 32)
    trilinear_kernel<<<dim3(2, 16, 32), 256>>>(out);
}